// round 7
// baseline (speedup 1.0000x reference)
#include <cuda_runtime.h>
#include <cuda_bf16.h>

#define H_IMG 96
#define W_IMG 96
#define C_IMG 1024
#define CV2   (C_IMG / 2)   // 512 float2 per pixel
#define POOL  7
#define NUM_ROIS 600

// One CTA per (roi, output position). 256 threads; thread t owns float2
// channel-slots t and t+256 -> 8 independent LDG.64 with only 16 data regs,
// so all 8 genuinely coexist under the 32-reg full-occupancy budget.
__global__ __launch_bounds__(256, 8)
void roi_pool_kernel(const float* __restrict__ img,
                     const int*   __restrict__ rois,
                     float*       __restrict__ out) {
    const int pos = blockIdx.x;        // 0..48
    const int roi = blockIdx.y;        // 0..599
    const int py  = pos / POOL;
    const int px  = pos % POOL;

    // roi = (x, y, w, h)
    const int4 r = __ldg(reinterpret_cast<const int4*>(rois) + roi);
    const int x = r.x;
    const int y = r.y;
    const int w = max(r.z, 1);
    const int h = max(r.w, 1);

    // TF1 resize semantics: src = dst * (in/out), align_corners=False
    const float in_y = (float)py * ((float)h / (float)POOL);
    const float in_x = (float)px * ((float)w / (float)POOL);
    const int y0 = (int)in_y;               // floor (nonnegative)
    const int x0 = (int)in_x;
    const int y1 = min(y0 + 1, h - 1);
    const int x1 = min(x0 + 1, w - 1);
    const float fy = in_y - (float)y0;
    const float fx = in_x - (float)x0;

    const int r0 = min(max(y + y0, 0), H_IMG - 1);
    const int r1 = min(max(y + y1, 0), H_IMG - 1);
    const int c0 = min(max(x + x0, 0), W_IMG - 1);
    const int c1 = min(max(x + x1, 0), W_IMG - 1);

    const int t = threadIdx.x;   // 0..255

    const float2* __restrict__ basev = reinterpret_cast<const float2*>(img);
    const float2* __restrict__ p00 = basev + ((size_t)r0 * W_IMG + c0) * CV2 + t;
    const float2* __restrict__ p01 = basev + ((size_t)r0 * W_IMG + c1) * CV2 + t;
    const float2* __restrict__ p10 = basev + ((size_t)r1 * W_IMG + c0) * CV2 + t;
    const float2* __restrict__ p11 = basev + ((size_t)r1 * W_IMG + c1) * CV2 + t;

    float2* __restrict__ o =
        reinterpret_cast<float2*>(out) + ((size_t)roi * (POOL * POOL) + pos) * CV2 + t;

    // 8 independent LDG.64 issued before any dependent math
    const float2 a0 = __ldg(p00);
    const float2 b0 = __ldg(p01);
    const float2 c0v = __ldg(p10);
    const float2 d0 = __ldg(p11);
    const float2 a1 = __ldg(p00 + 256);
    const float2 b1 = __ldg(p01 + 256);
    const float2 c1v = __ldg(p10 + 256);
    const float2 d1 = __ldg(p11 + 256);

    const float w00 = (1.0f - fx) * (1.0f - fy);
    const float w01 = fx * (1.0f - fy);
    const float w10 = (1.0f - fx) * fy;
    const float w11 = fx * fy;

    float2 r0v, r1v;
    r0v.x = a0.x * w00 + b0.x * w01 + c0v.x * w10 + d0.x * w11;
    r0v.y = a0.y * w00 + b0.y * w01 + c0v.y * w10 + d0.y * w11;

    r1v.x = a1.x * w00 + b1.x * w01 + c1v.x * w10 + d1.x * w11;
    r1v.y = a1.y * w00 + b1.y * w01 + c1v.y * w10 + d1.y * w11;

    o[0]   = r0v;
    o[256] = r1v;
}

extern "C" void kernel_launch(void* const* d_in, const int* in_sizes, int n_in,
                              void* d_out, int out_size) {
    const float* img  = (const float*)d_in[0];
    const int*   rois = (const int*)d_in[1];
    float*       out  = (float*)d_out;

    dim3 grid(POOL * POOL, NUM_ROIS);
    roi_pool_kernel<<<grid, 256>>>(img, rois, out);
}

// round 9
// speedup vs baseline: 1.1180x; 1.1180x over previous
#include <cuda_runtime.h>
#include <cuda_bf16.h>

#define H_IMG 96
#define W_IMG 96
#define C_IMG 1024
#define POOL  7
#define NUM_ROIS 600

// One CTA per (roi, output position). 128 threads; thread t owns float4
// channel-slots t and t+128 -> 8 independent LDG.128 per thread.
// maxBlocks=12 -> ~42-reg budget so the 8-load batch is NOT serialized by a
// 32-reg cap (R4's hidden flaw). Zero-weight corners are redirected to
// already-loaded addresses (branchless) so their loads become L1 hits.
__global__ __launch_bounds__(128, 12)
void roi_pool_kernel(const float* __restrict__ img,
                     const int*   __restrict__ rois,
                     float*       __restrict__ out) {
    const int pos = blockIdx.x;        // 0..48
    const int roi = blockIdx.y;        // 0..599
    const int py  = pos / POOL;
    const int px  = pos % POOL;

    // roi = (x, y, w, h)
    const int4 r = __ldg(reinterpret_cast<const int4*>(rois) + roi);
    const int x = r.x;
    const int y = r.y;
    const int w = max(r.z, 1);
    const int h = max(r.w, 1);

    // TF1 resize semantics: src = dst * (in/out), align_corners=False
    const float in_y = (float)py * ((float)h / (float)POOL);
    const float in_x = (float)px * ((float)w / (float)POOL);
    const int y0 = (int)in_y;               // floor (nonnegative)
    const int x0 = (int)in_x;
    const int y1 = min(y0 + 1, h - 1);
    const int x1 = min(x0 + 1, w - 1);
    const float fy = in_y - (float)y0;
    const float fx = in_x - (float)x0;

    const int r0 = min(max(y + y0, 0), H_IMG - 1);
    int       r1 = min(max(y + y1, 0), H_IMG - 1);
    const int c0 = min(max(x + x0, 0), W_IMG - 1);
    int       c1 = min(max(x + x1, 0), W_IMG - 1);

    // Branchless dedup: when a fraction is exactly 0, the corresponding
    // corner's weight is exactly 0, so redirect its load to the base corner
    // (same address -> L1 hit, no L2 traffic). Result is bitwise identical.
    if (fx == 0.0f) c1 = c0;
    if (fy == 0.0f) r1 = r0;

    const int t = threadIdx.x;   // 0..127

    const float4* __restrict__ p00 =
        reinterpret_cast<const float4*>(img + ((size_t)r0 * W_IMG + c0) * C_IMG) + t;
    const float4* __restrict__ p01 =
        reinterpret_cast<const float4*>(img + ((size_t)r0 * W_IMG + c1) * C_IMG) + t;
    const float4* __restrict__ p10 =
        reinterpret_cast<const float4*>(img + ((size_t)r1 * W_IMG + c0) * C_IMG) + t;
    const float4* __restrict__ p11 =
        reinterpret_cast<const float4*>(img + ((size_t)r1 * W_IMG + c1) * C_IMG) + t;

    float4* __restrict__ o =
        reinterpret_cast<float4*>(out + ((size_t)roi * (POOL * POOL) + pos) * C_IMG) + t;

    // 8 independent LDG.128 issued before any dependent math
    const float4 a0 = __ldg(p00);
    const float4 b0 = __ldg(p01);
    const float4 c0v = __ldg(p10);
    const float4 d0 = __ldg(p11);
    const float4 a1 = __ldg(p00 + 128);
    const float4 b1 = __ldg(p01 + 128);
    const float4 c1v = __ldg(p10 + 128);
    const float4 d1 = __ldg(p11 + 128);

    const float w00 = (1.0f - fx) * (1.0f - fy);
    const float w01 = fx * (1.0f - fy);
    const float w10 = (1.0f - fx) * fy;
    const float w11 = fx * fy;

    float4 r0v, r1v;
    r0v.x = a0.x * w00 + b0.x * w01 + c0v.x * w10 + d0.x * w11;
    r0v.y = a0.y * w00 + b0.y * w01 + c0v.y * w10 + d0.y * w11;
    r0v.z = a0.z * w00 + b0.z * w01 + c0v.z * w10 + d0.z * w11;
    r0v.w = a0.w * w00 + b0.w * w01 + c0v.w * w10 + d0.w * w11;

    r1v.x = a1.x * w00 + b1.x * w01 + c1v.x * w10 + d1.x * w11;
    r1v.y = a1.y * w00 + b1.y * w01 + c1v.y * w10 + d1.y * w11;
    r1v.z = a1.z * w00 + b1.z * w01 + c1v.z * w10 + d1.z * w11;
    r1v.w = a1.w * w00 + b1.w * w01 + c1v.w * w10 + d1.w * w11;

    o[0]   = r0v;
    o[128] = r1v;
}

extern "C" void kernel_launch(void* const* d_in, const int* in_sizes, int n_in,
                              void* d_out, int out_size) {
    const float* img  = (const float*)d_in[0];
    const int*   rois = (const int*)d_in[1];
    float*       out  = (float*)d_out;

    dim3 grid(POOL * POOL, NUM_ROIS);
    roi_pool_kernel<<<grid, 128>>>(img, rois, out);
}

// round 10
// speedup vs baseline: 1.1303x; 1.0110x over previous
#include <cuda_runtime.h>
#include <cuda_bf16.h>

#define H_IMG 96
#define W_IMG 96
#define C_IMG 1024
#define CV    (C_IMG / 4)   // 256 float4 per pixel
#define POOL  7
#define NUM_ROIS 600

// One CTA per (py, roi) -> 4200 CTAs. 128 threads; thread t owns float4
// channel-slots t and t+128. Rolled px loop: per iteration the proven
// 8x LDG.128 batch + 2 STG.128, with setup (roi decode, row pointers,
// 7 col offsets/fractions) amortized across 7 outputs.
// launch_bounds(128,10) -> 51-reg budget keeps the 8-load batch live.
__global__ __launch_bounds__(128, 10)
void roi_pool_kernel(const float* __restrict__ img,
                     const int*   __restrict__ rois,
                     float*       __restrict__ out) {
    const int py  = blockIdx.x;        // 0..6
    const int roi = blockIdx.y;        // 0..599

    __shared__ int   so0[POOL], so1[POOL];   // col offsets in float4 units
    __shared__ float sfx[POOL];
    __shared__ int   srow[2];                // r0, r1 pixel-row offsets
    __shared__ float sfy;

    if (threadIdx.x < POOL) {
        const int4 rr = __ldg(reinterpret_cast<const int4*>(rois) + roi);
        const int x = rr.x;
        const int y = rr.y;
        const int w = max(rr.z, 1);
        const int h = max(rr.w, 1);
        const int i = threadIdx.x;

        // horizontal for px = i (TF1 semantics: src = dst * in/out)
        const float in_x = (float)i * ((float)w / (float)POOL);
        const int   x0   = (int)in_x;
        const int   x1   = min(x0 + 1, w - 1);
        const float fx   = in_x - (float)x0;
        const int   c0   = min(max(x + x0, 0), W_IMG - 1);
        int         c1   = min(max(x + x1, 0), W_IMG - 1);
        if (fx == 0.0f) c1 = c0;          // zero-weight dedup -> L1 hit
        so0[i] = c0 * CV;
        so1[i] = c1 * CV;
        sfx[i] = fx;

        if (i == 0) {
            // vertical for this CTA's py
            const float in_y = (float)py * ((float)h / (float)POOL);
            const int   y0   = (int)in_y;
            const int   y1   = min(y0 + 1, h - 1);
            const float fy   = in_y - (float)y0;
            const int   r0   = min(max(y + y0, 0), H_IMG - 1);
            int         r1   = min(max(y + y1, 0), H_IMG - 1);
            if (fy == 0.0f) r1 = r0;      // zero-weight dedup
            srow[0] = r0 * W_IMG;
            srow[1] = r1 * W_IMG;
            sfy = fy;
        }
    }
    __syncthreads();

    const int t = threadIdx.x;   // 0..127
    const float fy = sfy;
    const float gy = 1.0f - fy;

    const float4* __restrict__ row0 =
        reinterpret_cast<const float4*>(img) + (size_t)srow[0] * CV + t;
    const float4* __restrict__ row1 =
        reinterpret_cast<const float4*>(img) + (size_t)srow[1] * CV + t;

    float4* __restrict__ o = reinterpret_cast<float4*>(out)
        + ((size_t)roi * (POOL * POOL) + (size_t)py * POOL) * CV + t;

    #pragma unroll 1
    for (int px = 0; px < POOL; ++px) {
        const int   o0 = so0[px];
        const int   o1 = so1[px];
        const float fx = sfx[px];

        // 8 independent LDG.128 batched before any dependent math
        const float4 a0 = __ldg(row0 + o0);
        const float4 b0 = __ldg(row0 + o1);
        const float4 c0v = __ldg(row1 + o0);
        const float4 d0 = __ldg(row1 + o1);
        const float4 a1 = __ldg(row0 + o0 + 128);
        const float4 b1 = __ldg(row0 + o1 + 128);
        const float4 c1v = __ldg(row1 + o0 + 128);
        const float4 d1 = __ldg(row1 + o1 + 128);

        const float w00 = (1.0f - fx) * gy;
        const float w01 = fx * gy;
        const float w10 = (1.0f - fx) * fy;
        const float w11 = fx * fy;

        float4 r0v, r1v;
        r0v.x = a0.x * w00 + b0.x * w01 + c0v.x * w10 + d0.x * w11;
        r0v.y = a0.y * w00 + b0.y * w01 + c0v.y * w10 + d0.y * w11;
        r0v.z = a0.z * w00 + b0.z * w01 + c0v.z * w10 + d0.z * w11;
        r0v.w = a0.w * w00 + b0.w * w01 + c0v.w * w10 + d0.w * w11;

        r1v.x = a1.x * w00 + b1.x * w01 + c1v.x * w10 + d1.x * w11;
        r1v.y = a1.y * w00 + b1.y * w01 + c1v.y * w10 + d1.y * w11;
        r1v.z = a1.z * w00 + b1.z * w01 + c1v.z * w10 + d1.z * w11;
        r1v.w = a1.w * w00 + b1.w * w01 + c1v.w * w10 + d1.w * w11;

        o[px * CV]       = r0v;
        o[px * CV + 128] = r1v;
    }
}

extern "C" void kernel_launch(void* const* d_in, const int* in_sizes, int n_in,
                              void* d_out, int out_size) {
    const float* img  = (const float*)d_in[0];
    const int*   rois = (const int*)d_in[1];
    float*       out  = (float*)d_out;

    dim3 grid(POOL, NUM_ROIS);
    roi_pool_kernel<<<grid, 128>>>(img, rois, out);
}